// round 13
// baseline (speedup 1.0000x reference)
#include <cuda_runtime.h>
#include <cstdint>

#define NBLK 592    // 148 SMs * 4 CTAs
#define NTHR 512

__device__ float g_sum;     // zero-init; reset by last block each run
__device__ int   g_cnt;
__device__ int   g_ticket;

__device__ __forceinline__ float4 ldg_nc_256_f4(const float4* p) {
    float4 v;
    asm volatile("ld.global.nc.L2::256B.v4.f32 {%0,%1,%2,%3}, [%4];"
                 : "=f"(v.x), "=f"(v.y), "=f"(v.z), "=f"(v.w)
                 : "l"(p));
    return v;
}

__device__ __forceinline__ int4 ldg_nc_256_i4(const int4* p) {
    int4 v;
    asm volatile("ld.global.nc.L2::256B.v4.b32 {%0,%1,%2,%3}, [%4];"
                 : "=r"(v.x), "=r"(v.y), "=r"(v.z), "=r"(v.w)
                 : "l"(p));
    return v;
}

// Accumulate log2-domain; scale by -ln2 once at the end.
__device__ __forceinline__ void bce_elem(float p, int t, float& s, int& c) {
    float q = (t == 1) ? p : (1.0f - p);     // argument select
    float l = __log2f(q);                    // single MUFU.LG2
    bool  keep = ((unsigned)t) < 2u;
    s += keep ? l : 0.0f;
    c += keep ? 1 : 0;
}

__global__ __launch_bounds__(NTHR) void bce_fused_kernel(
    const float* __restrict__ prob,
    const int* __restrict__ tgt,
    int n4,          // number of 4-element groups
    float* __restrict__ out)
{
    const float4* p4 = reinterpret_cast<const float4*>(prob);
    const int4*   t4 = reinterpret_cast<const int4*>(tgt);

    float s = 0.0f;  // sum of log2(q) over kept elements
    int   c = 0;

    int stride = gridDim.x * blockDim.x;
    for (int i = blockIdx.x * blockDim.x + threadIdx.x; i < n4; i += stride) {
        float4 p = ldg_nc_256_f4(&p4[i]);
        int4   t = ldg_nc_256_i4(&t4[i]);
        bce_elem(p.x, t.x, s, c);
        bce_elem(p.y, t.y, s, c);
        bce_elem(p.z, t.z, s, c);
        bce_elem(p.w, t.w, s, c);
    }

    // Convert to natural-log domain, negated: sum(-ln q) = -ln2 * sum(log2 q)
    s *= -0.69314718055994530942f;

    // Block reduction
    __shared__ float ss[NTHR];
    __shared__ int   sc[NTHR];
    int tid = threadIdx.x;
    ss[tid] = s;
    sc[tid] = c;
    __syncthreads();
    #pragma unroll
    for (int off = NTHR / 2; off >= 32; off >>= 1) {
        if (tid < off) {
            ss[tid] += ss[tid + off];
            sc[tid] += sc[tid + off];
        }
        __syncthreads();
    }
    if (tid < 32) {
        float ws = ss[tid];
        int   wc = sc[tid];
        #pragma unroll
        for (int off = 16; off > 0; off >>= 1) {
            ws += __shfl_down_sync(0xFFFFFFFFu, ws, off);
            wc += __shfl_down_sync(0xFFFFFFFFu, wc, off);
        }
        if (tid == 0) {
            // Per-block contribution straight to global accumulators.
            atomicAdd(&g_sum, ws);
            atomicAdd(&g_cnt, wc);
            __threadfence();
            int ticket = atomicAdd(&g_ticket, 1);
            if (ticket == gridDim.x - 1) {
                // All prior blocks' atomics are globally visible
                // (their fence precedes their ticket increment).
                float fs = g_sum;
                int   fc = g_cnt;
                out[0] = fs / (float)fc;
                // Reset for the next graph replay.
                atomicExch(&g_sum, 0.0f);
                atomicExch(&g_cnt, 0);
                atomicExch(&g_ticket, 0);
            }
        }
    }
}

extern "C" void kernel_launch(void* const* d_in, const int* in_sizes, int n_in,
                              void* d_out, int out_size) {
    const float* prob = (const float*)d_in[0];
    const int*   tgt  = (const int*)d_in[1];
    float*       out  = (float*)d_out;

    int n  = in_sizes[0];   // 40,960,000 (divisible by 4)
    int n4 = n / 4;

    bce_fused_kernel<<<NBLK, NTHR>>>(prob, tgt, n4, out);
}

// round 15
// speedup vs baseline: 1.0072x; 1.0072x over previous
#include <cuda_runtime.h>
#include <cstdint>

#define NBLK 296    // 148 SMs * 2 CTAs
#define NTHR 1024

__device__ float g_sum;     // zero-init; reset by last block each run
__device__ int   g_cnt;
__device__ int   g_ticket;

// Accumulate log2-domain; scale by -ln2 once at the end.
__device__ __forceinline__ void bce_elem(float p, int t, float& s, int& c) {
    float q = (t == 1) ? p : (1.0f - p);     // argument select
    float l = __log2f(q);                    // single MUFU.LG2
    bool  keep = ((unsigned)t) < 2u;
    s += keep ? l : 0.0f;
    c += keep ? 1 : 0;
}

__global__ __launch_bounds__(NTHR) void bce_fused_kernel(
    const float* __restrict__ prob,
    const int* __restrict__ tgt,
    int n4,          // number of 4-element groups
    float* __restrict__ out)
{
    const float4* p4 = reinterpret_cast<const float4*>(prob);
    const int4*   t4 = reinterpret_cast<const int4*>(tgt);

    float s = 0.0f;  // sum of log2(q) over kept elements
    int   c = 0;

    int stride = gridDim.x * blockDim.x;
    for (int i = blockIdx.x * blockDim.x + threadIdx.x; i < n4; i += stride) {
        float4 p = p4[i];
        int4   t = t4[i];
        bce_elem(p.x, t.x, s, c);
        bce_elem(p.y, t.y, s, c);
        bce_elem(p.z, t.z, s, c);
        bce_elem(p.w, t.w, s, c);
    }

    // Convert to natural-log domain, negated: sum(-ln q) = -ln2 * sum(log2 q)
    s *= -0.69314718055994530942f;

    // Block reduction
    __shared__ float ss[NTHR];
    __shared__ int   sc[NTHR];
    int tid = threadIdx.x;
    ss[tid] = s;
    sc[tid] = c;
    __syncthreads();
    #pragma unroll
    for (int off = NTHR / 2; off >= 32; off >>= 1) {
        if (tid < off) {
            ss[tid] += ss[tid + off];
            sc[tid] += sc[tid + off];
        }
        __syncthreads();
    }
    if (tid < 32) {
        float ws = ss[tid];
        int   wc = sc[tid];
        #pragma unroll
        for (int off = 16; off > 0; off >>= 1) {
            ws += __shfl_down_sync(0xFFFFFFFFu, ws, off);
            wc += __shfl_down_sync(0xFFFFFFFFu, wc, off);
        }
        if (tid == 0) {
            // Per-block contribution straight to global accumulators.
            atomicAdd(&g_sum, ws);
            atomicAdd(&g_cnt, wc);
            __threadfence();
            int ticket = atomicAdd(&g_ticket, 1);
            if (ticket == gridDim.x - 1) {
                // All prior blocks' atomics are globally visible
                // (their fence precedes their ticket increment).
                float fs = g_sum;
                int   fc = g_cnt;
                out[0] = fs / (float)fc;
                // Reset for the next graph replay.
                atomicExch(&g_sum, 0.0f);
                atomicExch(&g_cnt, 0);
                atomicExch(&g_ticket, 0);
            }
        }
    }
}

extern "C" void kernel_launch(void* const* d_in, const int* in_sizes, int n_in,
                              void* d_out, int out_size) {
    const float* prob = (const float*)d_in[0];
    const int*   tgt  = (const int*)d_in[1];
    float*       out  = (float*)d_out;

    int n  = in_sizes[0];   // 40,960,000 (divisible by 4)
    int n4 = n / 4;

    bce_fused_kernel<<<NBLK, NTHR>>>(prob, tgt, n4, out);
}